// round 2
// baseline (speedup 1.0000x reference)
#include <cuda_runtime.h>
#include <cuda_bf16.h>
#include <math.h>
#include <stdint.h>

// ---------------------------------------------------------------------------
// BitNet b1.58 MLP, exact-integer formulation.
//   bitlinear(x,w): per-token int8 activations (q in [-128,127], scale s)
//                   x per-tensor ternary weights (t in {-1,0,1}, scale ws)
//   => out = (int32 dot) * (1/s) * (1/ws)   (exact integer arithmetic)
// Round 2: double-precision reductions for the quantizer scales +
// reference-faithful fp32 op sequence in the quantizers (boundary flips
// were the round-1 failure at rel_err 1.78e-3).
// ---------------------------------------------------------------------------

#define Bq 2
#define Sq 2048
#define Dd 2048
#define Ff 8192
#define Mm (Bq*Sq)   // 4096

// scratch (device globals; no allocations allowed)
__device__ __align__(128) int8_t g_wq_gate[Ff * Dd];
__device__ __align__(128) int8_t g_wq_up[Ff * Dd];
__device__ __align__(128) int8_t g_wq_down[Dd * Ff];
__device__ __align__(128) int8_t g_xq[Mm * Dd];
__device__ __align__(128) int8_t g_hq[Mm * Ff];
__device__ __align__(128) float  g_G[(size_t)Mm * Ff];
__device__ __align__(128) float  g_U[(size_t)Mm * Ff];
__device__ float  g_xdq[Mm];
__device__ float  g_hdq[Mm];
__device__ double g_wsum[3];
__device__ float  g_wdq[3];

// -------------------------------- reductions -------------------------------

__device__ __forceinline__ double warpReduceSumD(double v) {
#pragma unroll
    for (int o = 16; o > 0; o >>= 1) v += __shfl_xor_sync(0xffffffffu, v, o);
    return v;
}
__device__ __forceinline__ float warpReduceMax(float v) {
#pragma unroll
    for (int o = 16; o > 0; o >>= 1) v = fmaxf(v, __shfl_xor_sync(0xffffffffu, v, o));
    return v;
}

__global__ void zero_scalars_kernel() {
    if (threadIdx.x < 3) g_wsum[threadIdx.x] = 0.0;
}

// sum of |w| over the whole tensor, double accumulation
__global__ void absum_kernel(const float* __restrict__ W, int n4, double* __restrict__ out) {
    double s = 0.0;
    const float4* W4 = (const float4*)W;
    for (int i = blockIdx.x * blockDim.x + threadIdx.x; i < n4; i += gridDim.x * blockDim.x) {
        float4 w = W4[i];
        // pairwise fp32 adds are exact enough per quad; accumulate quads in double
        s += (double)(fabsf(w.x) + fabsf(w.y)) + (double)(fabsf(w.z) + fabsf(w.w));
    }
    s = warpReduceSumD(s);
    __shared__ double rs[8];
    int warp = threadIdx.x >> 5, lane = threadIdx.x & 31;
    if (lane == 0) rs[warp] = s;
    __syncthreads();
    if (threadIdx.x == 0) {
        double t = 0.0;
#pragma unroll
        for (int i = 0; i < 8; i++) t += rs[i];
        atomicAdd(out, t);
    }
}

// ternary weight quant: scale = 1/clip(mean|w|,1e-5); t = rint(clip(w*scale,-1,1))
__global__ void wquant_kernel(const float* __restrict__ W, int8_t* __restrict__ Q, int n4,
                              const double* __restrict__ sumptr, double inv_n,
                              float* __restrict__ dq) {
    float mean = fmaxf((float)(*sumptr * inv_n), 1e-5f);
    float ws = 1.0f / mean;                 // reference: scale = fl(1/mean)
    int i = blockIdx.x * blockDim.x + threadIdx.x;
    if (i < n4) {
        float4 w = ((const float4*)W)[i];
        char4 q;
        q.x = (signed char)(int)rintf(fminf(fmaxf(w.x * ws, -1.0f), 1.0f));
        q.y = (signed char)(int)rintf(fminf(fmaxf(w.y * ws, -1.0f), 1.0f));
        q.z = (signed char)(int)rintf(fminf(fmaxf(w.z * ws, -1.0f), 1.0f));
        q.w = (signed char)(int)rintf(fminf(fmaxf(w.w * ws, -1.0f), 1.0f));
        ((char4*)Q)[i] = q;
    }
    if (i == 0) *dq = 1.0f / ws;            // reference dequant: fl(1/scale)
}

// numerically stable silu matching jax.nn.sigmoid's branch structure
__device__ __forceinline__ float silu_f(float g) {
    float sig;
    if (g >= 0.0f) {
        sig = 1.0f / (1.0f + expf(-g));
    } else {
        float e = expf(g);
        sig = e / (1.0f + e);
    }
    return g * sig;
}

// per-token: rmsnorm + int8 absmax quant.  fuse=1: input = silu(A_row) * Bu_row
// Reference-faithful sequence: r=fl(c*x); scale=fl(127/clip(fl(c*Mx),1e-5));
// v=fl(r*scale); q=rint(clip(v,-128,127)); dequant=fl(1/scale).
__global__ void __launch_bounds__(256) actquant_kernel(
        const float* __restrict__ A, const float* __restrict__ Bu,
        int8_t* __restrict__ Q, float* __restrict__ DQ, int D, int fuse) {
    __shared__ float sh[8192];
    __shared__ double rs[8];
    __shared__ float rm[8];
    __shared__ float s_c, s_scale;
    const int row = blockIdx.x;
    const float* a = A + (size_t)row * D;
    const float* bu = Bu ? (Bu + (size_t)row * D) : nullptr;
    double ss = 0.0;
    float mx = 0.0f;
    for (int i = threadIdx.x; i < D; i += blockDim.x) {
        float h;
        if (fuse) {
            h = silu_f(a[i]) * bu[i];
        } else {
            h = a[i];
        }
        sh[i] = h;
        ss += (double)h * (double)h;
        mx = fmaxf(mx, fabsf(h));
    }
    ss = warpReduceSumD(ss);
    mx = warpReduceMax(mx);
    int warp = threadIdx.x >> 5, lane = threadIdx.x & 31;
    if (lane == 0) { rs[warp] = ss; rm[warp] = mx; }
    __syncthreads();
    if (threadIdx.x == 0) {
        double S = 0.0;
        float Mx = 0.0f;
#pragma unroll
        for (int i = 0; i < 8; i++) { S += rs[i]; Mx = fmaxf(Mx, rm[i]); }
        float mean = (float)(S / (double)D);
        float c = rsqrtf(mean + 1e-6f);          // rmsnorm scalar (fp32, as ref)
        float m = fmaxf(c * Mx, 1e-5f);          // = max_i |fl(c*x_i)|, clipped
        float scale = 127.0f / m;                // reference association
        s_c = c; s_scale = scale;
        DQ[row] = 1.0f / scale;                  // reference dequant factor
    }
    __syncthreads();
    const float c = s_c, scale = s_scale;
    int8_t* q = Q + (size_t)row * D;
    for (int i = threadIdx.x; i < D; i += blockDim.x) {
        float r = c * sh[i];                     // fl(c*x)
        float v = r * scale;                     // fl(r*scale)
        q[i] = (int8_t)(int)rintf(fminf(fmaxf(v, -128.0f), 127.0f));
    }
}

// ------------------------------- int8 GEMM ---------------------------------
// C[M,N] = A[M,K](s8,row) . B[N,K](s8,row)^T  * adq[m] * (*wdq)
// BM=BN=128, BK=64 bytes (16 words), 256 threads, 8x8 per thread, dp4a.

#define BKW 16

__global__ void __launch_bounds__(256) gemm_s8_kernel(
        const int8_t* __restrict__ A, const int8_t* __restrict__ B,
        float* __restrict__ C, int M, int N, int K,
        const float* __restrict__ adq, const float* __restrict__ wdq) {
    __shared__ int As[128][BKW + 1];
    __shared__ int Bs[128][BKW + 1];
    const int tid = threadIdx.x;
    const int tx = tid & 15, ty = tid >> 4;
    const int bm = blockIdx.y * 128, bn = blockIdx.x * 128;
    const int K4 = K >> 2;

    int acc[8][8];
#pragma unroll
    for (int i = 0; i < 8; i++)
#pragma unroll
        for (int j = 0; j < 8; j++) acc[i][j] = 0;

    for (int ktw = 0; ktw < K4; ktw += BKW) {
#pragma unroll
        for (int it = 0; it < 2; it++) {
            int idx = it * 256 + tid;      // 0..511
            int row = idx >> 2, wq = idx & 3;
            const int4 va = *(const int4*)(A + (size_t)(bm + row) * K + ktw * 4 + wq * 16);
            As[row][wq * 4 + 0] = va.x; As[row][wq * 4 + 1] = va.y;
            As[row][wq * 4 + 2] = va.z; As[row][wq * 4 + 3] = va.w;
            const int4 vb = *(const int4*)(B + (size_t)(bn + row) * K + ktw * 4 + wq * 16);
            Bs[row][wq * 4 + 0] = vb.x; Bs[row][wq * 4 + 1] = vb.y;
            Bs[row][wq * 4 + 2] = vb.z; Bs[row][wq * 4 + 3] = vb.w;
        }
        __syncthreads();
#pragma unroll
        for (int w = 0; w < BKW; w++) {
            int a[8], b[8];
#pragma unroll
            for (int i = 0; i < 8; i++) a[i] = As[ty + 16 * i][w];
#pragma unroll
            for (int j = 0; j < 8; j++) b[j] = Bs[tx + 16 * j][w];
#pragma unroll
            for (int i = 0; i < 8; i++)
#pragma unroll
                for (int j = 0; j < 8; j++) acc[i][j] = __dp4a(a[i], b[j], acc[i][j]);
        }
        __syncthreads();
    }

    const float wsc = *wdq;
#pragma unroll
    for (int i = 0; i < 8; i++) {
        int r = bm + ty + 16 * i;
        float asc = adq[r] * wsc;
        float* crow = C + (size_t)r * N + bn;
#pragma unroll
        for (int j = 0; j < 8; j++) crow[tx + 16 * j] = (float)acc[i][j] * asc;
    }
}

// ------------------------------- launch ------------------------------------

extern "C" void kernel_launch(void* const* d_in, const int* in_sizes, int n_in,
                              void* d_out, int out_size) {
    const float* x  = (const float*)d_in[0];
    const float* wg = (const float*)d_in[1];
    const float* wu = (const float*)d_in[2];
    const float* wd = (const float*)d_in[3];
    float* out = (float*)d_out;

    int8_t *p_wqg, *p_wqu, *p_wqd, *p_xq, *p_hq;
    float *p_G, *p_U, *p_xdq, *p_hdq, *p_wdq;
    double *p_wsum;
    cudaGetSymbolAddress((void**)&p_wqg, g_wq_gate);
    cudaGetSymbolAddress((void**)&p_wqu, g_wq_up);
    cudaGetSymbolAddress((void**)&p_wqd, g_wq_down);
    cudaGetSymbolAddress((void**)&p_xq,  g_xq);
    cudaGetSymbolAddress((void**)&p_hq,  g_hq);
    cudaGetSymbolAddress((void**)&p_G,   g_G);
    cudaGetSymbolAddress((void**)&p_U,   g_U);
    cudaGetSymbolAddress((void**)&p_xdq, g_xdq);
    cudaGetSymbolAddress((void**)&p_hdq, g_hdq);
    cudaGetSymbolAddress((void**)&p_wsum, g_wsum);
    cudaGetSymbolAddress((void**)&p_wdq,  g_wdq);

    const int nW = Ff * Dd;          // 16777216 (each weight tensor)
    const int nW4 = nW / 4;

    zero_scalars_kernel<<<1, 32>>>();

    absum_kernel<<<2048, 256>>>(wg, nW4, p_wsum + 0);
    absum_kernel<<<2048, 256>>>(wu, nW4, p_wsum + 1);
    absum_kernel<<<2048, 256>>>(wd, nW4, p_wsum + 2);

    const double inv_n = 1.0 / (double)nW;
    wquant_kernel<<<(nW4 + 255) / 256, 256>>>(wg, p_wqg, nW4, p_wsum + 0, inv_n, p_wdq + 0);
    wquant_kernel<<<(nW4 + 255) / 256, 256>>>(wu, p_wqu, nW4, p_wsum + 1, inv_n, p_wdq + 1);
    wquant_kernel<<<(nW4 + 255) / 256, 256>>>(wd, p_wqd, nW4, p_wsum + 2, inv_n, p_wdq + 2);

    // per-token rmsnorm + quant of x
    actquant_kernel<<<Mm, 256>>>(x, nullptr, p_xq, p_xdq, Dd, 0);

    // gate and up GEMMs: [4096,8192] = [4096,2048] x [8192,2048]^T
    {
        dim3 grid(Ff / 128, Mm / 128);
        gemm_s8_kernel<<<grid, 256>>>(p_xq, p_wqg, p_G, Mm, Ff, Dd, p_xdq, p_wdq + 0);
        gemm_s8_kernel<<<grid, 256>>>(p_xq, p_wqu, p_U, Mm, Ff, Dd, p_xdq, p_wdq + 1);
    }

    // h = silu(G)*U, then rmsnorm + quant per row of F=8192
    actquant_kernel<<<Mm, 256>>>(p_G, p_U, p_hq, p_hdq, Ff, 1);

    // down GEMM: [4096,2048] = [4096,8192] x [2048,8192]^T -> d_out
    {
        dim3 grid(Dd / 128, Mm / 128);
        gemm_s8_kernel<<<grid, 256>>>(p_hq, p_wqd, out, Mm, Dd, Ff, p_hdq, p_wdq + 2);
    }
}

// round 6
// speedup vs baseline: 1.1558x; 1.1558x over previous
#include <cuda_runtime.h>
#include <cuda_bf16.h>
#include <math.h>
#include <stdint.h>

// ---------------------------------------------------------------------------
// BitNet b1.58 MLP, exact-integer formulation on legacy IMMA
// (mma.sync.m16n8k32.s8 -- baseline PTX, works with the harness's sm_103
// ptxas target; tcgen05 is rejected there, learned round 3).
//   q in [-128,127] int8, t in {-1,0,1} int8, int32 accum => exact.
// Pipeline: absum -> wquant -> actquant(x) -> IMMA gate (writes dequant G)
//           -> IMMA up (epilogue H = silu(G)*u) -> actquant(H)
//           -> IMMA down -> d_out
// ---------------------------------------------------------------------------

#define Dd 2048
#define Ff 8192
#define Mm 4096

__device__ __align__(128) int8_t g_wq_gate[Ff * Dd];
__device__ __align__(128) int8_t g_wq_up[Ff * Dd];
__device__ __align__(128) int8_t g_wq_down[Dd * Ff];
__device__ __align__(128) int8_t g_xq[Mm * Dd];
__device__ __align__(128) int8_t g_hq[Mm * Ff];
__device__ __align__(128) float  g_G[(size_t)Mm * Ff];
__device__ __align__(128) float  g_H[(size_t)Mm * Ff];
__device__ float  g_xdq[Mm];
__device__ float  g_hdq[Mm];
__device__ double g_wsum[3];
__device__ float  g_wdq[3];

// ------------------------------ utilities ----------------------------------

__device__ __forceinline__ uint32_t smem_u32(const void* p) {
    uint32_t a;
    asm("{ .reg .u64 t; cvta.to.shared.u64 t, %1; cvt.u32.u64 %0, t; }"
        : "=r"(a) : "l"(p));
    return a;
}
__device__ __forceinline__ void cp16(uint32_t dst, const void* src) {
    asm volatile("cp.async.cg.shared.global [%0], [%1], 16;"
                 :: "r"(dst), "l"(src) : "memory");
}
__device__ __forceinline__ void cp_commit() {
    asm volatile("cp.async.commit_group;" ::: "memory");
}
__device__ __forceinline__ void cp_wait2() {
    asm volatile("cp.async.wait_group 2;" ::: "memory");
}
__device__ __forceinline__ uint32_t lds32(uint32_t addr) {
    uint32_t v;
    asm volatile("ld.shared.b32 %0, [%1];" : "=r"(v) : "r"(addr));
    return v;
}
__device__ __forceinline__ void mma_s8(int* c, const uint32_t* a, const uint32_t* b) {
    asm volatile(
        "mma.sync.aligned.m16n8k32.row.col.s32.s8.s8.s32 "
        "{%0,%1,%2,%3}, {%4,%5,%6,%7}, {%8,%9}, {%0,%1,%2,%3};"
        : "+r"(c[0]), "+r"(c[1]), "+r"(c[2]), "+r"(c[3])
        : "r"(a[0]), "r"(a[1]), "r"(a[2]), "r"(a[3]), "r"(b[0]), "r"(b[1]));
}

__device__ __forceinline__ double warpReduceSumD(double v) {
#pragma unroll
    for (int o = 16; o > 0; o >>= 1) v += __shfl_xor_sync(0xffffffffu, v, o);
    return v;
}
__device__ __forceinline__ float warpReduceMax(float v) {
#pragma unroll
    for (int o = 16; o > 0; o >>= 1) v = fmaxf(v, __shfl_xor_sync(0xffffffffu, v, o));
    return v;
}
__device__ __forceinline__ float silu_f(float g) {
    float sig;
    if (g >= 0.0f) {
        sig = 1.0f / (1.0f + expf(-g));
    } else {
        float e = expf(g);
        sig = e / (1.0f + e);
    }
    return g * sig;
}

// ---------------------------- small kernels --------------------------------

__global__ void zero_scalars_kernel() {
    if (threadIdx.x < 3) g_wsum[threadIdx.x] = 0.0;
}

__global__ void absum3_kernel(const float* __restrict__ W0, const float* __restrict__ W1,
                              const float* __restrict__ W2, int n4) {
    const float* W = (blockIdx.y == 0) ? W0 : (blockIdx.y == 1) ? W1 : W2;
    double s = 0.0;
    const float4* W4 = (const float4*)W;
    for (int i = blockIdx.x * blockDim.x + threadIdx.x; i < n4;
         i += gridDim.x * blockDim.x) {
        float4 w = W4[i];
        s += (double)(fabsf(w.x) + fabsf(w.y)) + (double)(fabsf(w.z) + fabsf(w.w));
    }
    s = warpReduceSumD(s);
    __shared__ double rs[8];
    int warp = threadIdx.x >> 5, lane = threadIdx.x & 31;
    if (lane == 0) rs[warp] = s;
    __syncthreads();
    if (threadIdx.x == 0) {
        double t = 0.0;
#pragma unroll
        for (int i = 0; i < 8; i++) t += rs[i];
        atomicAdd(&g_wsum[blockIdx.y], t);
    }
}

__global__ void wquant3_kernel(const float* __restrict__ W0, const float* __restrict__ W1,
                               const float* __restrict__ W2,
                               int8_t* __restrict__ Q0, int8_t* __restrict__ Q1,
                               int8_t* __restrict__ Q2,
                               int n4, double inv_n) {
    const int y = blockIdx.y;
    const float* W = (y == 0) ? W0 : (y == 1) ? W1 : W2;
    int8_t* Q = (y == 0) ? Q0 : (y == 1) ? Q1 : Q2;
    float mean = fmaxf((float)(g_wsum[y] * inv_n), 1e-5f);
    float ws = 1.0f / mean;
    int i = blockIdx.x * blockDim.x + threadIdx.x;
    if (i < n4) {
        float4 w = ((const float4*)W)[i];
        char4 q;
        q.x = (signed char)(int)rintf(fminf(fmaxf(w.x * ws, -1.0f), 1.0f));
        q.y = (signed char)(int)rintf(fminf(fmaxf(w.y * ws, -1.0f), 1.0f));
        q.z = (signed char)(int)rintf(fminf(fmaxf(w.z * ws, -1.0f), 1.0f));
        q.w = (signed char)(int)rintf(fminf(fmaxf(w.w * ws, -1.0f), 1.0f));
        ((char4*)Q)[i] = q;
    }
    if (i == 0) g_wdq[y] = 1.0f / ws;
}

// per-token rmsnorm + int8 absmax quant (reference-faithful fp32 sequence)
__global__ void __launch_bounds__(256) actquant_kernel(
        const float* __restrict__ A, int8_t* __restrict__ Q,
        float* __restrict__ DQ, int D) {
    __shared__ float sh[8192];
    __shared__ double rs[8];
    __shared__ float rm[8];
    __shared__ float s_c, s_scale;
    const int row = blockIdx.x;
    const float* a = A + (size_t)row * D;
    double ss = 0.0;
    float mx = 0.0f;
    for (int i = threadIdx.x; i < D; i += blockDim.x) {
        float h = a[i];
        sh[i] = h;
        ss += (double)h * (double)h;
        mx = fmaxf(mx, fabsf(h));
    }
    ss = warpReduceSumD(ss);
    mx = warpReduceMax(mx);
    int warp = threadIdx.x >> 5, lane = threadIdx.x & 31;
    if (lane == 0) { rs[warp] = ss; rm[warp] = mx; }
    __syncthreads();
    if (threadIdx.x == 0) {
        double S = 0.0;
        float Mx = 0.0f;
#pragma unroll
        for (int i = 0; i < 8; i++) { S += rs[i]; Mx = fmaxf(Mx, rm[i]); }
        float mean = (float)(S / (double)D);
        float c = rsqrtf(mean + 1e-6f);
        float m = fmaxf(c * Mx, 1e-5f);
        float scale = 127.0f / m;
        s_c = c; s_scale = scale;
        DQ[row] = 1.0f / scale;
    }
    __syncthreads();
    const float c = s_c, scale = s_scale;
    int8_t* q = Q + (size_t)row * D;
    for (int i = threadIdx.x; i < D; i += blockDim.x) {
        float r = c * sh[i];
        float v = r * scale;
        q[i] = (int8_t)(int)rintf(fminf(fmaxf(v, -128.0f), 127.0f));
    }
}

// ------------------------------ IMMA GEMM ----------------------------------
// C[M,N] = A[M,K](s8 row) . B[N,K](s8 row)^T, scaled; optional fused silu:
// FUSE=1: C = silu(Gin) * (acc*scale)   (the "up" projection)
// BM=BN=128, BK=64, 256 threads, warp grid 2x4, warp tile 64x32,
// mma.m16n8k32, 4-stage cp.async pipeline.
// smem row stride 80B (20 words) -> conflict-free fragment LDS.

#define STAGES 4
#define STG_BYTES 20480   // A 10240 + B 10240 per stage
#define GEMM_SMEM (STAGES * STG_BYTES)

template<int FUSE>
__global__ void __launch_bounds__(256, 2) gemm_imma_kernel(
        const int8_t* __restrict__ A, const int8_t* __restrict__ B,
        float* __restrict__ C, const float* __restrict__ Gin,
        int K, const float* __restrict__ adq, const float* __restrict__ wdq) {
    extern __shared__ __align__(128) char smem[];
    const uint32_t sbase = smem_u32(smem);
    const int tid = threadIdx.x;
    const int lane = tid & 31;
    const int g = lane >> 2, tig = lane & 3;
    const int w = tid >> 5;
    const int wm = w >> 2, wn = w & 3;
    const int bm = blockIdx.y * 128, bn = blockIdx.x * 128;
    const int N = gridDim.x * 128;

    int acc[4][4][4];
#pragma unroll
    for (int mt = 0; mt < 4; mt++)
#pragma unroll
        for (int nt = 0; nt < 4; nt++)
#pragma unroll
            for (int k = 0; k < 4; k++) acc[mt][nt][k] = 0;

    const int r_ld = tid >> 2;        // 0..63 rows per half
    const int wq_ld = tid & 3;        // 16B chunk within 64B row

    auto LOAD = [&](int kc, int s) {
        uint32_t sa = sbase + s * STG_BYTES;
        uint32_t sb = sa + 10240;
        const int8_t* Ag = A + (size_t)bm * K + (size_t)kc * 64;
        const int8_t* Bg = B + (size_t)bn * K + (size_t)kc * 64;
#pragma unroll
        for (int i = 0; i < 2; i++) {
            int row = r_ld + i * 64;
            cp16(sa + row * 80 + wq_ld * 16, Ag + (size_t)row * K + wq_ld * 16);
            cp16(sb + row * 80 + wq_ld * 16, Bg + (size_t)row * K + wq_ld * 16);
        }
        cp_commit();
    };

    const int NK = K >> 6;
    LOAD(0, 0); LOAD(1, 1); LOAD(2, 2);

    for (int kc = 0; kc < NK; kc++) {
        cp_wait2();
        __syncthreads();
        if (kc + 3 < NK) LOAD(kc + 3, (kc + 3) & 3); else cp_commit();

        const uint32_t sa = sbase + (kc & 3) * STG_BYTES;
        const uint32_t sb = sa + 10240;
#pragma unroll
        for (int ks = 0; ks < 2; ks++) {
            uint32_t af[4][4], bf[4][2];
#pragma unroll
            for (int mt = 0; mt < 4; mt++) {
                uint32_t base = sa + (uint32_t)(wm * 64 + mt * 16 + g) * 80
                              + (uint32_t)(ks * 8 + tig) * 4;
                af[mt][0] = lds32(base);
                af[mt][1] = lds32(base + 8 * 80);
                af[mt][2] = lds32(base + 16);
                af[mt][3] = lds32(base + 8 * 80 + 16);
            }
#pragma unroll
            for (int nt = 0; nt < 4; nt++) {
                uint32_t base = sb + (uint32_t)(wn * 32 + nt * 8 + g) * 80
                              + (uint32_t)(ks * 8 + tig) * 4;
                bf[nt][0] = lds32(base);
                bf[nt][1] = lds32(base + 16);
            }
#pragma unroll
            for (int mt = 0; mt < 4; mt++)
#pragma unroll
                for (int nt = 0; nt < 4; nt++)
                    mma_s8(acc[mt][nt], af[mt], bf[nt]);
        }
    }

    // epilogue
    const float wsc = *wdq;
#pragma unroll
    for (int mt = 0; mt < 4; mt++) {
        const int r0 = bm + wm * 64 + mt * 16 + g;
        const int r1 = r0 + 8;
        const float s0 = adq[r0] * wsc;
        const float s1 = adq[r1] * wsc;
#pragma unroll
        for (int nt = 0; nt < 4; nt++) {
            const int c = bn + wn * 32 + nt * 8 + tig * 2;
            float v00 = (float)acc[mt][nt][0] * s0;
            float v01 = (float)acc[mt][nt][1] * s0;
            float v10 = (float)acc[mt][nt][2] * s1;
            float v11 = (float)acc[mt][nt][3] * s1;
            if (FUSE) {
                float2 g0 = *(const float2*)&Gin[(size_t)r0 * N + c];
                float2 g1 = *(const float2*)&Gin[(size_t)r1 * N + c];
                v00 = silu_f(g0.x) * v00;
                v01 = silu_f(g0.y) * v01;
                v10 = silu_f(g1.x) * v10;
                v11 = silu_f(g1.y) * v11;
            }
            *(float2*)&C[(size_t)r0 * N + c] = make_float2(v00, v01);
            *(float2*)&C[(size_t)r1 * N + c] = make_float2(v10, v11);
        }
    }
}

// ------------------------------- launch ------------------------------------

extern "C" void kernel_launch(void* const* d_in, const int* in_sizes, int n_in,
                              void* d_out, int out_size) {
    const float* x  = (const float*)d_in[0];
    const float* wg = (const float*)d_in[1];
    const float* wu = (const float*)d_in[2];
    const float* wd = (const float*)d_in[3];
    float* out = (float*)d_out;

    int8_t *p_wqg, *p_wqu, *p_wqd, *p_xq, *p_hq;
    float *p_G, *p_H, *p_xdq, *p_hdq, *p_wdq;
    cudaGetSymbolAddress((void**)&p_wqg, g_wq_gate);
    cudaGetSymbolAddress((void**)&p_wqu, g_wq_up);
    cudaGetSymbolAddress((void**)&p_wqd, g_wq_down);
    cudaGetSymbolAddress((void**)&p_xq,  g_xq);
    cudaGetSymbolAddress((void**)&p_hq,  g_hq);
    cudaGetSymbolAddress((void**)&p_G,   g_G);
    cudaGetSymbolAddress((void**)&p_H,   g_H);
    cudaGetSymbolAddress((void**)&p_xdq, g_xdq);
    cudaGetSymbolAddress((void**)&p_hdq, g_hdq);
    cudaGetSymbolAddress((void**)&p_wdq, g_wdq);

    cudaFuncSetAttribute(gemm_imma_kernel<0>,
                         cudaFuncAttributeMaxDynamicSharedMemorySize, GEMM_SMEM);
    cudaFuncSetAttribute(gemm_imma_kernel<1>,
                         cudaFuncAttributeMaxDynamicSharedMemorySize, GEMM_SMEM);

    const int nW = Ff * Dd;
    const int nW4 = nW / 4;

    zero_scalars_kernel<<<1, 32>>>();
    absum3_kernel<<<dim3(2048, 3), 256>>>(wg, wu, wd, nW4);
    wquant3_kernel<<<dim3(nW4 / 256, 3), 256>>>(wg, wu, wd, p_wqg, p_wqu, p_wqd,
                                                nW4, 1.0 / (double)nW);

    actquant_kernel<<<Mm, 256>>>(x, p_xq, p_xdq, Dd);

    // gate: G = dequant(acc)    [4096, 8192]
    gemm_imma_kernel<0><<<dim3(Ff / 128, Mm / 128), 256, GEMM_SMEM>>>(
        p_xq, p_wqg, p_G, nullptr, Dd, p_xdq, p_wdq + 0);

    // up (fused): H = silu(G) * dequant(acc)
    gemm_imma_kernel<1><<<dim3(Ff / 128, Mm / 128), 256, GEMM_SMEM>>>(
        p_xq, p_wqu, p_H, p_G, Dd, p_xdq, p_wdq + 1);

    actquant_kernel<<<Mm, 256>>>(p_H, p_hq, p_hdq, Ff);

    // down -> d_out  [4096, 2048]
    gemm_imma_kernel<0><<<dim3(Dd / 128, Mm / 128), 256, GEMM_SMEM>>>(
        p_hq, p_wqd, out, nullptr, Ff, p_hdq, p_wdq + 2);
}

// round 8
// speedup vs baseline: 2.3115x; 2.0000x over previous
#include <cuda_runtime.h>
#include <cuda_bf16.h>
#include <math.h>
#include <stdint.h>

// ---------------------------------------------------------------------------
// BitNet b1.58 MLP, exact-integer formulation on legacy bf16 HMMA
// (mma.sync.m16n8k16.f32.bf16.bf16.f32 -- baseline PTX for the sm_103
// ptxas target; tcgen05 rejected (R3), legacy s8 IMMA runs at dp4a rate (R6)).
//   activation codes in [-128,127] and ternary weights {-1,0,1} are exact
//   bf16; products <=127 exact; fp32 accum of ints < 2^24 exact
//   => bit-identical to the int32 formulation (rel_err 5.6e-4 in R2/R6).
// ---------------------------------------------------------------------------

#define Dd 2048
#define Ff 8192
#define Mm 4096

__device__ __align__(128) __nv_bfloat16 g_wgb[Ff * Dd];
__device__ __align__(128) __nv_bfloat16 g_wub[Ff * Dd];
__device__ __align__(128) __nv_bfloat16 g_wdb[Dd * Ff];
__device__ __align__(128) __nv_bfloat16 g_xb[Mm * Dd];
__device__ __align__(128) __nv_bfloat16 g_hb[(size_t)Mm * Ff];
__device__ __align__(128) float g_G[(size_t)Mm * Ff];
__device__ __align__(128) float g_H[(size_t)Mm * Ff];
__device__ float  g_xdq[Mm];
__device__ float  g_hdq[Mm];
__device__ double g_wsum[3];
__device__ float  g_wdq[3];

// ------------------------------ utilities ----------------------------------

__device__ __forceinline__ uint32_t smem_u32(const void* p) {
    uint32_t a;
    asm("{ .reg .u64 t; cvta.to.shared.u64 t, %1; cvt.u32.u64 %0, t; }"
        : "=r"(a) : "l"(p));
    return a;
}
__device__ __forceinline__ void cp16(uint32_t dst, const void* src) {
    asm volatile("cp.async.cg.shared.global [%0], [%1], 16;"
                 :: "r"(dst), "l"(src) : "memory");
}
__device__ __forceinline__ void cp_commit() {
    asm volatile("cp.async.commit_group;" ::: "memory");
}
__device__ __forceinline__ void cp_wait1() {
    asm volatile("cp.async.wait_group 1;" ::: "memory");
}
__device__ __forceinline__ uint32_t lds32(uint32_t addr) {
    uint32_t v;
    asm volatile("ld.shared.b32 %0, [%1];" : "=r"(v) : "r"(addr));
    return v;
}
__device__ __forceinline__ void mma_bf16(float* c, const uint32_t* a, const uint32_t* b) {
    asm volatile(
        "mma.sync.aligned.m16n8k16.row.col.f32.bf16.bf16.f32 "
        "{%0,%1,%2,%3}, {%4,%5,%6,%7}, {%8,%9}, {%0,%1,%2,%3};"
        : "+f"(c[0]), "+f"(c[1]), "+f"(c[2]), "+f"(c[3])
        : "r"(a[0]), "r"(a[1]), "r"(a[2]), "r"(a[3]), "r"(b[0]), "r"(b[1]));
}

__device__ __forceinline__ double warpReduceSumD(double v) {
#pragma unroll
    for (int o = 16; o > 0; o >>= 1) v += __shfl_xor_sync(0xffffffffu, v, o);
    return v;
}
__device__ __forceinline__ float warpReduceMax(float v) {
#pragma unroll
    for (int o = 16; o > 0; o >>= 1) v = fmaxf(v, __shfl_xor_sync(0xffffffffu, v, o));
    return v;
}
__device__ __forceinline__ float silu_f(float g) {
    float sig;
    if (g >= 0.0f) {
        sig = 1.0f / (1.0f + expf(-g));
    } else {
        float e = expf(g);
        sig = e / (1.0f + e);
    }
    return g * sig;
}

// ---------------------------- small kernels --------------------------------

__global__ void zero_scalars_kernel() {
    if (threadIdx.x < 3) g_wsum[threadIdx.x] = 0.0;
}

__global__ void absum3_kernel(const float* __restrict__ W0, const float* __restrict__ W1,
                              const float* __restrict__ W2, int n4) {
    const float* W = (blockIdx.y == 0) ? W0 : (blockIdx.y == 1) ? W1 : W2;
    double s = 0.0;
    const float4* W4 = (const float4*)W;
    for (int i = blockIdx.x * blockDim.x + threadIdx.x; i < n4;
         i += gridDim.x * blockDim.x) {
        float4 w = W4[i];
        s += (double)(fabsf(w.x) + fabsf(w.y)) + (double)(fabsf(w.z) + fabsf(w.w));
    }
    s = warpReduceSumD(s);
    __shared__ double rs[8];
    int warp = threadIdx.x >> 5, lane = threadIdx.x & 31;
    if (lane == 0) rs[warp] = s;
    __syncthreads();
    if (threadIdx.x == 0) {
        double t = 0.0;
#pragma unroll
        for (int i = 0; i < 8; i++) t += rs[i];
        atomicAdd(&g_wsum[blockIdx.y], t);
    }
}

// ternary weight quant -> bf16 {-1,0,1}
__global__ void wquant3_kernel(const float* __restrict__ W0, const float* __restrict__ W1,
                               const float* __restrict__ W2,
                               __nv_bfloat16* __restrict__ Q0,
                               __nv_bfloat16* __restrict__ Q1,
                               __nv_bfloat16* __restrict__ Q2,
                               int n4, double inv_n) {
    const int y = blockIdx.y;
    const float* W = (y == 0) ? W0 : (y == 1) ? W1 : W2;
    __nv_bfloat16* Q = (y == 0) ? Q0 : (y == 1) ? Q1 : Q2;
    float mean = fmaxf((float)(g_wsum[y] * inv_n), 1e-5f);
    float ws = 1.0f / mean;
    int i = blockIdx.x * blockDim.x + threadIdx.x;
    if (i < n4) {
        float4 w = ((const float4*)W)[i];
        float qx = rintf(fminf(fmaxf(w.x * ws, -1.0f), 1.0f));
        float qy = rintf(fminf(fmaxf(w.y * ws, -1.0f), 1.0f));
        float qz = rintf(fminf(fmaxf(w.z * ws, -1.0f), 1.0f));
        float qw = rintf(fminf(fmaxf(w.w * ws, -1.0f), 1.0f));
        __nv_bfloat162 lo = __nv_bfloat162(__float2bfloat16(qx), __float2bfloat16(qy));
        __nv_bfloat162 hi = __nv_bfloat162(__float2bfloat16(qz), __float2bfloat16(qw));
        uint2 pk;
        pk.x = *(uint32_t*)&lo;
        pk.y = *(uint32_t*)&hi;
        ((uint2*)Q)[i] = pk;
    }
    if (i == 0) g_wdq[y] = 1.0f / ws;
}

// per-token rmsnorm + int8 absmax quant; codes emitted as bf16 (exact ints)
__global__ void __launch_bounds__(256) actquant_kernel(
        const float* __restrict__ A, __nv_bfloat16* __restrict__ Q,
        float* __restrict__ DQ, int D) {
    __shared__ float sh[8192];
    __shared__ double rs[8];
    __shared__ float rm[8];
    __shared__ float s_c, s_scale;
    const int row = blockIdx.x;
    const float* a = A + (size_t)row * D;
    double ss = 0.0;
    float mx = 0.0f;
    for (int i = threadIdx.x; i < D; i += blockDim.x) {
        float h = a[i];
        sh[i] = h;
        ss += (double)h * (double)h;
        mx = fmaxf(mx, fabsf(h));
    }
    ss = warpReduceSumD(ss);
    mx = warpReduceMax(mx);
    int warp = threadIdx.x >> 5, lane = threadIdx.x & 31;
    if (lane == 0) { rs[warp] = ss; rm[warp] = mx; }
    __syncthreads();
    if (threadIdx.x == 0) {
        double S = 0.0;
        float Mx = 0.0f;
#pragma unroll
        for (int i = 0; i < 8; i++) { S += rs[i]; Mx = fmaxf(Mx, rm[i]); }
        float mean = (float)(S / (double)D);
        float c = rsqrtf(mean + 1e-6f);
        float m = fmaxf(c * Mx, 1e-5f);
        float scale = 127.0f / m;
        s_c = c; s_scale = scale;
        DQ[row] = 1.0f / scale;
    }
    __syncthreads();
    const float c = s_c, scale = s_scale;
    __nv_bfloat16* q = Q + (size_t)row * D;
    for (int i = threadIdx.x; i < D; i += blockDim.x) {
        float r = c * sh[i];
        float v = r * scale;
        q[i] = __float2bfloat16(rintf(fminf(fmaxf(v, -128.0f), 127.0f)));
    }
}

// --------------------------- bf16 HMMA GEMM --------------------------------
// C[M,N] = A[M,K](bf16 row) . B[N,K](bf16 row)^T, scaled.
// FUSE=1: C = silu(Gin) * (acc*scale)
// BM=BN=128, BK=64 elems (128B rows, smem stride 144B), 256 threads,
// warp grid 2x4, warp tile 64x32, mma.m16n8k16.bf16, 3-stage cp.async.

#define ROWB 144
#define TILEB (128 * ROWB)     // 18432
#define STG_BYTES (2 * TILEB)  // 36864
#define GEMM_SMEM (3 * STG_BYTES)

template<int FUSE>
__global__ void __launch_bounds__(256, 2) gemm_bf16_kernel(
        const __nv_bfloat16* __restrict__ A, const __nv_bfloat16* __restrict__ B,
        float* __restrict__ C, const float* __restrict__ Gin,
        int K, const float* __restrict__ adq, const float* __restrict__ wdq) {
    extern __shared__ __align__(128) char smem[];
    const uint32_t sbase = smem_u32(smem);
    const int tid = threadIdx.x;
    const int lane = tid & 31;
    const int g = lane >> 2, tig = lane & 3;
    const int w = tid >> 5;
    const int wm = w >> 2, wn = w & 3;
    const int bm = blockIdx.y * 128, bn = blockIdx.x * 128;
    const int N = gridDim.x * 128;
    const size_t Kb = (size_t)K * 2;     // bytes per global row

    float acc[4][4][4];
#pragma unroll
    for (int mt = 0; mt < 4; mt++)
#pragma unroll
        for (int nt = 0; nt < 4; nt++)
#pragma unroll
            for (int k = 0; k < 4; k++) acc[mt][nt][k] = 0.0f;

    const int lr = tid >> 3;           // 0..31
    const int lc = (tid & 7) * 16;     // 16B chunk in 128B row

    auto LOAD = [&](int kc, int s) {
        uint32_t sa = sbase + s * STG_BYTES;
        uint32_t sb = sa + TILEB;
        const char* Ag = (const char*)A + (size_t)bm * Kb + (size_t)kc * 128;
        const char* Bg = (const char*)B + (size_t)bn * Kb + (size_t)kc * 128;
#pragma unroll
        for (int i = 0; i < 4; i++) {
            int row = lr + i * 32;
            cp16(sa + row * ROWB + lc, Ag + (size_t)row * Kb + lc);
            cp16(sb + row * ROWB + lc, Bg + (size_t)row * Kb + lc);
        }
        cp_commit();
    };

    const int NK = K >> 6;
    LOAD(0, 0); LOAD(1, 1);

    int cs = 0;            // stage of current kc
    for (int kc = 0; kc < NK; kc++) {
        cp_wait1();
        __syncthreads();
        int ls = cs + 2; if (ls >= 3) ls -= 3;
        if (kc + 2 < NK) LOAD(kc + 2, ls); else cp_commit();

        const uint32_t sa = sbase + cs * STG_BYTES;
        const uint32_t sb = sa + TILEB;
#pragma unroll
        for (int ks = 0; ks < 4; ks++) {
            uint32_t af[4][4], bfr[4][2];
#pragma unroll
            for (int mt = 0; mt < 4; mt++) {
                uint32_t base = sa + (uint32_t)(wm * 64 + mt * 16 + g) * ROWB
                              + (uint32_t)(ks * 32 + tig * 4);
                af[mt][0] = lds32(base);
                af[mt][1] = lds32(base + 8 * ROWB);
                af[mt][2] = lds32(base + 16);
                af[mt][3] = lds32(base + 8 * ROWB + 16);
            }
#pragma unroll
            for (int nt = 0; nt < 4; nt++) {
                uint32_t base = sb + (uint32_t)(wn * 32 + nt * 8 + g) * ROWB
                              + (uint32_t)(ks * 32 + tig * 4);
                bfr[nt][0] = lds32(base);
                bfr[nt][1] = lds32(base + 16);
            }
#pragma unroll
            for (int mt = 0; mt < 4; mt++)
#pragma unroll
                for (int nt = 0; nt < 4; nt++)
                    mma_bf16(acc[mt][nt], af[mt], bfr[nt]);
        }
        cs++; if (cs == 3) cs = 0;
    }

    // epilogue
    const float wsc = *wdq;
#pragma unroll
    for (int mt = 0; mt < 4; mt++) {
        const int r0 = bm + wm * 64 + mt * 16 + g;
        const int r1 = r0 + 8;
        const float s0 = adq[r0] * wsc;
        const float s1 = adq[r1] * wsc;
#pragma unroll
        for (int nt = 0; nt < 4; nt++) {
            const int c = bn + wn * 32 + nt * 8 + tig * 2;
            float v00 = acc[mt][nt][0] * s0;
            float v01 = acc[mt][nt][1] * s0;
            float v10 = acc[mt][nt][2] * s1;
            float v11 = acc[mt][nt][3] * s1;
            if (FUSE) {
                float2 g0 = *(const float2*)&Gin[(size_t)r0 * N + c];
                float2 g1 = *(const float2*)&Gin[(size_t)r1 * N + c];
                v00 = silu_f(g0.x) * v00;
                v01 = silu_f(g0.y) * v01;
                v10 = silu_f(g1.x) * v10;
                v11 = silu_f(g1.y) * v11;
            }
            *(float2*)&C[(size_t)r0 * N + c] = make_float2(v00, v01);
            *(float2*)&C[(size_t)r1 * N + c] = make_float2(v10, v11);
        }
    }
}

// ------------------------------- launch ------------------------------------

extern "C" void kernel_launch(void* const* d_in, const int* in_sizes, int n_in,
                              void* d_out, int out_size) {
    const float* x  = (const float*)d_in[0];
    const float* wg = (const float*)d_in[1];
    const float* wu = (const float*)d_in[2];
    const float* wd = (const float*)d_in[3];
    float* out = (float*)d_out;

    __nv_bfloat16 *p_wgb, *p_wub, *p_wdb, *p_xb, *p_hb;
    float *p_G, *p_H, *p_xdq, *p_hdq, *p_wdq;
    cudaGetSymbolAddress((void**)&p_wgb, g_wgb);
    cudaGetSymbolAddress((void**)&p_wub, g_wub);
    cudaGetSymbolAddress((void**)&p_wdb, g_wdb);
    cudaGetSymbolAddress((void**)&p_xb,  g_xb);
    cudaGetSymbolAddress((void**)&p_hb,  g_hb);
    cudaGetSymbolAddress((void**)&p_G,   g_G);
    cudaGetSymbolAddress((void**)&p_H,   g_H);
    cudaGetSymbolAddress((void**)&p_xdq, g_xdq);
    cudaGetSymbolAddress((void**)&p_hdq, g_hdq);
    cudaGetSymbolAddress((void**)&p_wdq, g_wdq);

    cudaFuncSetAttribute(gemm_bf16_kernel<0>,
                         cudaFuncAttributeMaxDynamicSharedMemorySize, GEMM_SMEM);
    cudaFuncSetAttribute(gemm_bf16_kernel<1>,
                         cudaFuncAttributeMaxDynamicSharedMemorySize, GEMM_SMEM);

    const int nW = Ff * Dd;
    const int nW4 = nW / 4;

    zero_scalars_kernel<<<1, 32>>>();
    absum3_kernel<<<dim3(2048, 3), 256>>>(wg, wu, wd, nW4);
    wquant3_kernel<<<dim3(nW4 / 256, 3), 256>>>(wg, wu, wd, p_wgb, p_wub, p_wdb,
                                                nW4, 1.0 / (double)nW);

    actquant_kernel<<<Mm, 256>>>(x, p_xb, p_xdq, Dd);

    // gate: G = dequant(acc)    [4096, 8192]
    gemm_bf16_kernel<0><<<dim3(Ff / 128, Mm / 128), 256, GEMM_SMEM>>>(
        p_xb, p_wgb, p_G, nullptr, Dd, p_xdq, p_wdq + 0);

    // up (fused): H = silu(G) * dequant(acc)
    gemm_bf16_kernel<1><<<dim3(Ff / 128, Mm / 128), 256, GEMM_SMEM>>>(
        p_xb, p_wub, p_H, p_G, Dd, p_xdq, p_wdq + 1);

    actquant_kernel<<<Mm, 256>>>(p_H, p_hb, p_hdq, Ff);

    // down -> d_out  [4096, 2048]
    gemm_bf16_kernel<0><<<dim3(Dd / 128, Mm / 128), 256, GEMM_SMEM>>>(
        p_hb, p_wdb, out, p_hdq, Ff, p_hdq, p_wdq + 2);
}